// round 9
// baseline (speedup 1.0000x reference)
#include <cuda_runtime.h>
#include <cuda_fp16.h>
#include <math.h>
#include <stdint.h>

// Problem dims (fixed)
#define Bv 32
#define Sv 1024
#define Dv 1024
#define Av 256
#define Ev 16
#define Mrows (Bv * Sv)   // 32768

// ---------------------------------------------------------------------------
// Persistent scratch (no cudaMalloc allowed)
// ---------------------------------------------------------------------------
__device__ float g_pre[(size_t)Mrows * Dv];          // pre-LN fp32
__device__ __half g_h1[(size_t)Mrows * Av];          // stage1 out fp16
__device__ __half g_h2[(size_t)Mrows * Av];          // stage2 out fp16
__device__ __half g_dwh[Av * Dv];                    // down_W fp16
__device__ __half g_uwh[Dv * Av];                    // up_W fp16
__device__ __half g_ewh[Ev * Av * Av];               // expert_W fp16
__device__ int g_idx[Bv];
__device__ int g_valid[Bv];

// ---------------------------------------------------------------------------
__device__ __forceinline__ uint32_t smem_u32(const void* p) {
    uint32_t a;
    asm("{ .reg .u64 t; cvta.to.shared.u64 t, %1; cvt.u32.u64 %0, t; }" : "=r"(a) : "l"(p));
    return a;
}
#define LDSM4(r, addr) \
    asm volatile("ldmatrix.sync.aligned.m8n8.x4.shared.b16 {%0,%1,%2,%3}, [%4];" \
        : "=r"((r)[0]), "=r"((r)[1]), "=r"((r)[2]), "=r"((r)[3]) : "r"(addr))
#define MMA_OP(d, a, b0, b1) \
    asm volatile("mma.sync.aligned.m16n8k16.row.col.f32.f16.f16.f32 " \
        "{%0,%1,%2,%3}, {%4,%5,%6,%7}, {%8,%9}, {%0,%1,%2,%3};" \
        : "+f"((d)[0]), "+f"((d)[1]), "+f"((d)[2]), "+f"((d)[3]) \
        : "r"((a)[0]), "r"((a)[1]), "r"((a)[2]), "r"((a)[3]), "r"(b0), "r"(b1))
#define CP16(dst, src) \
    asm volatile("cp.async.cg.shared.global [%0], [%1], 16;" :: "r"(dst), "l"(src))
#define CPCOMMIT() asm volatile("cp.async.commit_group;" ::: "memory")
#define CPWAIT0()  asm volatile("cp.async.wait_group 0;" ::: "memory")

// ---------------------------------------------------------------------------
// domain_id may arrive as int32 or int64. Detect and normalize.
// ---------------------------------------------------------------------------
__global__ void prep_ids(const int* __restrict__ p) {
    bool is64 = true;
    for (int k = 0; k < 16; k++) {
        int hi = p[2 * k + 1];
        if (hi != 0 && hi != -1) { is64 = false; break; }
    }
    for (int b = 0; b < Bv; b++) {
        long long v;
        if (is64) {
            unsigned int lo = (unsigned int)p[2 * b];
            int hi = p[2 * b + 1];
            v = ((long long)hi << 32) | (long long)lo;
        } else {
            v = p[b];
        }
        g_valid[b] = (v >= 0 && v < Ev) ? 1 : 0;
        long long c = v < 0 ? 0 : (v > (Ev - 1) ? (Ev - 1) : v);
        g_idx[b] = (int)c;
    }
}

// Convert fp32 weights to fp16, vectorized float4 -> 4 halves.
__global__ void conv_w(const float* __restrict__ src,
                       __half* __restrict__ H, int n4) {
    for (int i = blockIdx.x * blockDim.x + threadIdx.x; i < n4;
         i += gridDim.x * blockDim.x) {
        float4 v = ((const float4*)src)[i];
        __half2 h0 = __floats2half2_rn(v.x, v.y);
        __half2 h1 = __floats2half2_rn(v.z, v.w);
        ((uint2*)H)[i] = make_uint2(*(uint32_t*)&h0, *(uint32_t*)&h1);
    }
}

__device__ __forceinline__ float gelu_exact(float v) {
    return 0.5f * v * (1.0f + erff(v * 0.70710678118654752440f));
}

// Convert fp32 float4 -> 4 fp16, store 8B (swizzle-safe).
__device__ __forceinline__ void conv_store(char* base, uint32_t off, float4 v) {
    __half2 h0 = __floats2half2_rn(v.x, v.y);
    __half2 h1 = __floats2half2_rn(v.z, v.w);
    *(uint2*)(base + off) = make_uint2(*(uint32_t*)&h0, *(uint32_t*)&h1);
}

// cp.async loaders into swizzled SMEM (512 threads).
// 128-row fp16 tile: 1024 lines of 16B -> 2 iters.
__device__ __forceinline__ void load_hi128(uint32_t dst,
                                           const __half* __restrict__ hi,
                                           int tid, int K, int k0) {
#pragma unroll
    for (int i = 0; i < 2; i++) {
        const int idx = tid + i * 512;
        const int row = idx >> 3;
        const int c8 = idx & 7;
        const uint32_t off = (uint32_t)(row * 128) +
                             (uint32_t)((c8 * 16) ^ ((row & 7) << 4));
        CP16(dst + off, hi + (size_t)row * K + k0 + c8 * 8);
    }
}
// 256-row fp16 tile: 2048 lines -> 4 iters.
__device__ __forceinline__ void load_hi256(uint32_t dst,
                                           const __half* __restrict__ hi,
                                           int tid, int K, int k0) {
#pragma unroll
    for (int i = 0; i < 4; i++) {
        const int idx = tid + i * 512;
        const int row = idx >> 3;
        const int c8 = idx & 7;
        const uint32_t off = (uint32_t)(row * 128) +
                             (uint32_t)((c8 * 16) ^ ((row & 7) << 4));
        CP16(dst + off, hi + (size_t)row * K + k0 + c8 * 8);
    }
}

// ---------------------------------------------------------------------------
// fp16 NT GEMM via mma.sync: C[128,256] = A[M,K] * B[N,K]^T, fp32 accum.
// 512 threads, 16 warps 4(M)x4(N); warp tile 32x64 (mt=2 x nt=8).
// BK=64, 2-stage cp.async. SMEM stage: A(16K) B(32K) = 48KB; x2 = 96KB.
// MODE 1: A = hidden fp32 (in-loop convert), B = down_W; GELU -> g_h1
// MODE 2: A = g_h1, B = expert_W[e]; +bias/pass + emb -> g_h2
// MODE 3: A = g_h2, B = up_W; +bias+residual -> g_pre fp32
// ---------------------------------------------------------------------------
#define A_OFF 0u
#define BH_OFF 16384u
#define STAGE_B 49152u
#define SMEM_BYTES (2u * STAGE_B)

template <int MODE>
__global__ __launch_bounds__(512, 1)
void hmma_gemm(const float* __restrict__ Afp,
               const float* __restrict__ bias,
               const float* __restrict__ extra) {
    constexpr int K  = (MODE == 1) ? Dv : Av;
    constexpr int N  = (MODE == 3) ? Dv : Av;
    constexpr int NC = K / 64;

    extern __shared__ char sm[];
    const uint32_t sbase = smem_u32(sm);

    const int tid  = threadIdx.x;
    const int lane = tid & 31;
    const int wid  = tid >> 5;
    const int wm   = wid & 3;     // warp row: 4 x 32 = 128 M
    const int wn   = wid >> 2;    // warp col: 4 x 64 = 256 N

    int m0;
    const int n0 = blockIdx.x * 256;
    const __half *Ah = nullptr, *Bh;
    const float* biasp = bias;
    const float* embp = nullptr;
    int valid = 1;
    if (MODE == 1) {
        m0 = blockIdx.y * 128;
        Bh = g_dwh;
    } else if (MODE == 2) {
        const int b = blockIdx.z;
        const int e = g_idx[b];
        valid = g_valid[b];
        m0 = b * Sv + blockIdx.y * 128;
        Ah = g_h1;
        Bh = g_ewh + (size_t)e * Av * Av;
        biasp = bias + (size_t)e * Av;
        embp = extra + (size_t)e * Av;
    } else {
        m0 = blockIdx.y * 128;
        Ah = g_h2;
        Bh = g_uwh;
    }

    const float* ArowF = (MODE == 1) ? (Afp + (size_t)m0 * K) : nullptr;
    const __half* ArowH = (MODE != 1) ? (Ah + (size_t)m0 * K) : nullptr;
    const __half* BrowH = Bh + (size_t)n0 * K;

    // MODE1 A convert coords (128x64 fp32 -> 2048 float4, 4/thread)
    int lr[4], lc[4];
    uint32_t soff[4];
    float4 pA[4];
    if (MODE == 1) {
#pragma unroll
        for (int i = 0; i < 4; i++) {
            const int idx = tid + i * 512;
            lr[i] = idx >> 4;
            lc[i] = (idx & 15) * 4;
            soff[i] = (uint32_t)(lr[i] * 128) +
                      (uint32_t)((lc[i] * 2) ^ ((lr[i] & 7) << 4));
            pA[i] = *(const float4*)(ArowF + (size_t)lr[i] * K + lc[i]);
        }
    }

    // Prologue: issue chunk 0 copies
    {
        if (MODE != 1) load_hi128(sbase + A_OFF, ArowH, tid, K, 0);
        load_hi256(sbase + BH_OFF, BrowH, tid, K, 0);
        CPCOMMIT();
    }

    float acc[2][8][4];
#pragma unroll
    for (int mt = 0; mt < 2; mt++)
#pragma unroll
        for (int nt = 0; nt < 8; nt++)
#pragma unroll
            for (int q = 0; q < 4; q++) acc[mt][nt][q] = 0.f;

    for (int c = 0; c < NC; c++) {
        const int s = c & 1;
        const uint32_t sb = sbase + s * STAGE_B;

        if (MODE == 1) {
            char* smc = sm + s * STAGE_B;
#pragma unroll
            for (int i = 0; i < 4; i++)
                conv_store(smc + A_OFF, soff[i], pA[i]);
        }
        CPWAIT0();
        __syncthreads();

        if (c + 1 < NC) {
            const uint32_t nb = sbase + (s ^ 1) * STAGE_B;
            const int k0 = (c + 1) * 64;
            if (MODE != 1) load_hi128(nb + A_OFF, ArowH, tid, K, k0);
            load_hi256(nb + BH_OFF, BrowH, tid, K, k0);
            CPCOMMIT();
            if (MODE == 1) {
#pragma unroll
                for (int i = 0; i < 4; i++)
                    pA[i] = *(const float4*)(ArowF + (size_t)lr[i] * K + k0 + lc[i]);
            }
        }

        // compute chunk: 4 k16 steps, warp tile 32x64
#pragma unroll
        for (int k16 = 0; k16 < 4; k16++) {
            uint32_t ah[2][4], bh[4][4];
#pragma unroll
            for (int mt = 0; mt < 2; mt++) {
                const int row = wm * 32 + mt * 16 + (lane & 15);
                const int kc  = k16 * 16 + (lane >> 4) * 8;
                const uint32_t off = (uint32_t)(row * 128) +
                                     (uint32_t)((kc * 2) ^ ((row & 7) << 4));
                LDSM4(ah[mt], sb + A_OFF + off);
            }
#pragma unroll
            for (int p = 0; p < 4; p++) {
                const int g    = lane >> 3;
                const int nrow = wn * 64 + p * 16 + (g >> 1) * 8 + (lane & 7);
                const int kc   = k16 * 16 + (g & 1) * 8;
                const uint32_t off = (uint32_t)(nrow * 128) +
                                     (uint32_t)((kc * 2) ^ ((nrow & 7) << 4));
                LDSM4(bh[p], sb + BH_OFF + off);
            }
#pragma unroll
            for (int mt = 0; mt < 2; mt++)
#pragma unroll
                for (int nt = 0; nt < 8; nt++) {
                    const int p = nt >> 1;
                    const int q = (nt & 1) * 2;
                    MMA_OP(acc[mt][nt], ah[mt], bh[p][q], bh[p][q + 1]);
                }
        }
        __syncthreads();
    }

    // ---- epilogue ----
#pragma unroll
    for (int mt = 0; mt < 2; mt++)
#pragma unroll
        for (int half = 0; half < 2; half++) {
            const int r = m0 + wm * 32 + mt * 16 + (lane >> 2) + half * 8;
#pragma unroll
            for (int nt = 0; nt < 8; nt++) {
                const int col = n0 + wn * 64 + nt * 8 + (lane & 3) * 2;
                float vx = acc[mt][nt][half * 2];
                float vy = acc[mt][nt][half * 2 + 1];
                if (MODE == 1) {
                    const float2 bi = *(const float2*)(bias + col);
                    vx = gelu_exact(vx + bi.x);
                    vy = gelu_exact(vy + bi.y);
                    __half2 h = __floats2half2_rn(vx, vy);
                    *(uint32_t*)(g_h1 + (size_t)r * Av + col) = *(uint32_t*)&h;
                } else if (MODE == 2) {
                    if (valid) {
                        const float2 bi = *(const float2*)(biasp + col);
                        vx += bi.x; vy += bi.y;
                    } else {
                        uint32_t ph = *(const uint32_t*)(g_h1 + (size_t)r * Av + col);
                        float2 fh = __half22float2(*(__half2*)&ph);
                        vx = fh.x; vy = fh.y;
                    }
                    const float2 em = *(const float2*)(embp + col);
                    vx += em.x; vy += em.y;
                    __half2 h = __floats2half2_rn(vx, vy);
                    *(uint32_t*)(g_h2 + (size_t)r * Av + col) = *(uint32_t*)&h;
                } else {
                    const float2 bi = *(const float2*)(bias + col);
                    const float2 rs = *(const float2*)(extra + (size_t)r * Dv + col);
                    vx += bi.x + rs.x;
                    vy += bi.y + rs.y;
                    *(float2*)(g_pre + (size_t)r * N + col) = make_float2(vx, vy);
                }
            }
        }
}

// ---------------------------------------------------------------------------
// LayerNorm over D=1024 (one 256-thread block per row, 4 elems/thread)
// ---------------------------------------------------------------------------
__global__ __launch_bounds__(256)
void ln_kernel(const float* __restrict__ gamma,
               const float* __restrict__ beta,
               float* __restrict__ out) {
    const int row = blockIdx.x;
    const int t = threadIdx.x;
    const float4 v = *(const float4*)(g_pre + (size_t)row * Dv + t * 4);

    __shared__ float red1[8];
    __shared__ float red2[8];

    float s = v.x + v.y + v.z + v.w;
#pragma unroll
    for (int o = 16; o; o >>= 1) s += __shfl_xor_sync(0xFFFFFFFFu, s, o);
    if ((t & 31) == 0) red1[t >> 5] = s;
    __syncthreads();
    float tot = 0.f;
#pragma unroll
    for (int i = 0; i < 8; i++) tot += red1[i];
    const float mu = tot * (1.0f / Dv);

    const float dx = v.x - mu, dy = v.y - mu, dz = v.z - mu, dw = v.w - mu;
    float s2 = dx * dx + dy * dy + dz * dz + dw * dw;
#pragma unroll
    for (int o = 16; o; o >>= 1) s2 += __shfl_xor_sync(0xFFFFFFFFu, s2, o);
    if ((t & 31) == 0) red2[t >> 5] = s2;
    __syncthreads();
    float tot2 = 0.f;
#pragma unroll
    for (int i = 0; i < 8; i++) tot2 += red2[i];
    const float inv = rsqrtf(tot2 * (1.0f / Dv) + 1e-5f);

    const int c = t * 4;
    const float4 gm = *(const float4*)(gamma + c);
    const float4 bt = *(const float4*)(beta + c);
    float4 o;
    o.x = dx * inv * gm.x + bt.x;
    o.y = dy * inv * gm.y + bt.y;
    o.z = dz * inv * gm.z + bt.z;
    o.w = dw * inv * gm.w + bt.w;
    *(float4*)(out + (size_t)row * Dv + c) = o;
}

// ---------------------------------------------------------------------------
extern "C" void kernel_launch(void* const* d_in, const int* in_sizes, int n_in,
                              void* d_out, int out_size) {
    const float* hidden     = (const float*)d_in[0];
    const int*   dom        = (const int*)d_in[1];
    const float* down_W     = (const float*)d_in[2];
    const float* down_b     = (const float*)d_in[3];
    const float* up_W       = (const float*)d_in[4];
    const float* up_b       = (const float*)d_in[5];
    const float* expert_W   = (const float*)d_in[6];
    const float* expert_b   = (const float*)d_in[7];
    const float* domain_emb = (const float*)d_in[8];
    const float* gamma      = (const float*)d_in[9];
    const float* beta       = (const float*)d_in[10];
    float* out = (float*)d_out;

    cudaFuncSetAttribute(hmma_gemm<1>, cudaFuncAttributeMaxDynamicSharedMemorySize, SMEM_BYTES);
    cudaFuncSetAttribute(hmma_gemm<2>, cudaFuncAttributeMaxDynamicSharedMemorySize, SMEM_BYTES);
    cudaFuncSetAttribute(hmma_gemm<3>, cudaFuncAttributeMaxDynamicSharedMemorySize, SMEM_BYTES);

    prep_ids<<<1, 1>>>(dom);

    // one-time weight conversions (fp16)
    __half *dwh, *uwh, *ewh;
    cudaGetSymbolAddress((void**)&dwh, g_dwh);
    cudaGetSymbolAddress((void**)&uwh, g_uwh);
    cudaGetSymbolAddress((void**)&ewh, g_ewh);
    conv_w<<<128, 512>>>(down_W, dwh, Av * Dv / 4);
    conv_w<<<128, 512>>>(up_W, uwh, Dv * Av / 4);
    conv_w<<<256, 512>>>(expert_W, ewh, Ev * Av * Av / 4);

    // Stage 1: down-proj + GELU   (M=32768, N=256,  K=1024)
    hmma_gemm<1><<<dim3(1, Mrows / 128), 512, SMEM_BYTES>>>(hidden, down_b, nullptr);
    // Stage 2: per-batch expert   (per batch M=1024, N=256, K=256)
    hmma_gemm<2><<<dim3(1, Sv / 128, Bv), 512, SMEM_BYTES>>>(nullptr, expert_b, domain_emb);
    // Stage 3: up-proj + residual (M=32768, N=1024, K=256)
    hmma_gemm<3><<<dim3(Dv / 256, Mrows / 128), 512, SMEM_BYTES>>>(nullptr, up_b, hidden);
    // Stage 4: LayerNorm
    ln_kernel<<<Mrows, 256>>>(gamma, beta, out);
}

// round 10
// speedup vs baseline: 1.1025x; 1.1025x over previous
#include <cuda_runtime.h>
#include <cuda_fp16.h>
#include <math.h>
#include <stdint.h>

// Problem dims (fixed)
#define Bv 32
#define Sv 1024
#define Dv 1024
#define Av 256
#define Ev 16
#define Mrows (Bv * Sv)   // 32768

// ---------------------------------------------------------------------------
// Persistent scratch (no cudaMalloc allowed)
// ---------------------------------------------------------------------------
__device__ __half g_h2[(size_t)Mrows * Av];          // stage1+2 out fp16
__device__ __half g_uo[(size_t)Mrows * Dv];          // up-proj out fp16 (no residual)
__device__ __half g_dwh[Av * Dv];                    // down_W fp16
__device__ __half g_uwh[Dv * Av];                    // up_W fp16
__device__ __half g_ewh[Ev * Av * Av];               // expert_W fp16
__device__ int g_idx[Bv];
__device__ int g_valid[Bv];

// ---------------------------------------------------------------------------
__device__ __forceinline__ uint32_t smem_u32(const void* p) {
    uint32_t a;
    asm("{ .reg .u64 t; cvta.to.shared.u64 t, %1; cvt.u32.u64 %0, t; }" : "=r"(a) : "l"(p));
    return a;
}
#define LDSM4(r, addr) \
    asm volatile("ldmatrix.sync.aligned.m8n8.x4.shared.b16 {%0,%1,%2,%3}, [%4];" \
        : "=r"((r)[0]), "=r"((r)[1]), "=r"((r)[2]), "=r"((r)[3]) : "r"(addr))
#define MMA_OP(d, a, b0, b1) \
    asm volatile("mma.sync.aligned.m16n8k16.row.col.f32.f16.f16.f32 " \
        "{%0,%1,%2,%3}, {%4,%5,%6,%7}, {%8,%9}, {%0,%1,%2,%3};" \
        : "+f"((d)[0]), "+f"((d)[1]), "+f"((d)[2]), "+f"((d)[3]) \
        : "r"((a)[0]), "r"((a)[1]), "r"((a)[2]), "r"((a)[3]), "r"(b0), "r"(b1))
#define CP16(dst, src) \
    asm volatile("cp.async.cg.shared.global [%0], [%1], 16;" :: "r"(dst), "l"(src))
#define CPCOMMIT() asm volatile("cp.async.commit_group;" ::: "memory")
#define CPWAIT0()  asm volatile("cp.async.wait_group 0;" ::: "memory")

// SMEM layout (bytes)
#define A_OFF 0u
#define BH_OFF 16384u
#define STAGE_B 49152u                 // per pipeline stage: A 16K + B 32K
#define H1_OFF (2u * STAGE_B)          // 98304: h1 tile, 4 chunks x 16KB
#define SMEM_FUSED (H1_OFF + 65536u)   // 163840
#define SMEM_S3 (2u * STAGE_B)         // 98304

// ---------------------------------------------------------------------------
// domain_id may arrive as int32 or int64. Detect and normalize.
// ---------------------------------------------------------------------------
__global__ void prep_ids(const int* __restrict__ p) {
    bool is64 = true;
    for (int k = 0; k < 16; k++) {
        int hi = p[2 * k + 1];
        if (hi != 0 && hi != -1) { is64 = false; break; }
    }
    for (int b = 0; b < Bv; b++) {
        long long v;
        if (is64) {
            unsigned int lo = (unsigned int)p[2 * b];
            int hi = p[2 * b + 1];
            v = ((long long)hi << 32) | (long long)lo;
        } else {
            v = p[b];
        }
        g_valid[b] = (v >= 0 && v < Ev) ? 1 : 0;
        long long c = v < 0 ? 0 : (v > (Ev - 1) ? (Ev - 1) : v);
        g_idx[b] = (int)c;
    }
}

// Convert fp32 weights to fp16, vectorized float4 -> 4 halves.
__global__ void conv_w(const float* __restrict__ src,
                       __half* __restrict__ H, int n4) {
    for (int i = blockIdx.x * blockDim.x + threadIdx.x; i < n4;
         i += gridDim.x * blockDim.x) {
        float4 v = ((const float4*)src)[i];
        __half2 h0 = __floats2half2_rn(v.x, v.y);
        __half2 h1 = __floats2half2_rn(v.z, v.w);
        ((uint2*)H)[i] = make_uint2(*(uint32_t*)&h0, *(uint32_t*)&h1);
    }
}

__device__ __forceinline__ float gelu_exact(float v) {
    return 0.5f * v * (1.0f + erff(v * 0.70710678118654752440f));
}

// Convert fp32 float4 -> 4 fp16, store 8B (swizzle-safe).
__device__ __forceinline__ void conv_store(char* base, uint32_t off, float4 v) {
    __half2 h0 = __floats2half2_rn(v.x, v.y);
    __half2 h1 = __floats2half2_rn(v.z, v.w);
    *(uint2*)(base + off) = make_uint2(*(uint32_t*)&h0, *(uint32_t*)&h1);
}

// cp.async loaders into swizzled SMEM (512 threads).
__device__ __forceinline__ void load_hi128(uint32_t dst,
                                           const __half* __restrict__ hi,
                                           int tid, int K, int k0) {
#pragma unroll
    for (int i = 0; i < 2; i++) {
        const int idx = tid + i * 512;
        const int row = idx >> 3;
        const int c8 = idx & 7;
        const uint32_t off = (uint32_t)(row * 128) +
                             (uint32_t)((c8 * 16) ^ ((row & 7) << 4));
        CP16(dst + off, hi + (size_t)row * K + k0 + c8 * 8);
    }
}
__device__ __forceinline__ void load_hi256(uint32_t dst,
                                           const __half* __restrict__ hi,
                                           int tid, int K, int k0) {
#pragma unroll
    for (int i = 0; i < 4; i++) {
        const int idx = tid + i * 512;
        const int row = idx >> 3;
        const int c8 = idx & 7;
        const uint32_t off = (uint32_t)(row * 128) +
                             (uint32_t)((c8 * 16) ^ ((row & 7) << 4));
        CP16(dst + off, hi + (size_t)row * K + k0 + c8 * 8);
    }
}

// ---------------------------------------------------------------------------
// Fused stages 1+2: one block owns 128 rows x full A=256 cols.
//   GEMM1: h1 = GELU(hidden * down_W^T + down_b)   (K=1024, in-loop A convert)
//   h1 kept in SMEM (fp16, swizzled, 4 chunk regions of 128x64)
//   GEMM2: h2 = h1 * expert_W[e]^T + b_e (or passthrough) + emb  -> g_h2 fp16
// 512 threads, 16 warps 4(M)x4(N), warp tile 32x64.
// ---------------------------------------------------------------------------
__global__ __launch_bounds__(512, 1)
void fused_s12(const float* __restrict__ Afp,
               const float* __restrict__ down_b,
               const float* __restrict__ expert_b,
               const float* __restrict__ domain_emb) {
    constexpr int K1 = Dv;     // 1024
    constexpr int NC1 = K1 / 64;

    extern __shared__ char sm[];
    const uint32_t sbase = smem_u32(sm);

    const int tid  = threadIdx.x;
    const int lane = tid & 31;
    const int wid  = tid >> 5;
    const int wm   = wid & 3;
    const int wn   = wid >> 2;

    const int m0 = blockIdx.y * 128;
    const int b  = m0 >> 10;            // / Sv
    const int e  = g_idx[b];
    const int valid = g_valid[b];

    const float* ArowF = Afp + (size_t)m0 * K1;
    const __half* BrowH = g_dwh;        // 256 rows x 1024 K
    const __half* Brow2 = g_ewh + (size_t)e * Av * Av;
    const float* biasp = expert_b + (size_t)e * Av;
    const float* embp  = domain_emb + (size_t)e * Av;

    // A convert coords (128x64 fp32 -> 2048 float4, 4/thread)
    int lr[4], lc[4];
    uint32_t soff[4];
    float4 pA[4];
#pragma unroll
    for (int i = 0; i < 4; i++) {
        const int idx = tid + i * 512;
        lr[i] = idx >> 4;
        lc[i] = (idx & 15) * 4;
        soff[i] = (uint32_t)(lr[i] * 128) +
                  (uint32_t)((lc[i] * 2) ^ ((lr[i] & 7) << 4));
        pA[i] = *(const float4*)(ArowF + (size_t)lr[i] * K1 + lc[i]);
    }

    // Prologue: B chunk 0
    load_hi256(sbase + BH_OFF, BrowH, tid, K1, 0);
    CPCOMMIT();

    float acc[2][8][4];
#pragma unroll
    for (int mt = 0; mt < 2; mt++)
#pragma unroll
        for (int nt = 0; nt < 8; nt++)
#pragma unroll
            for (int q = 0; q < 4; q++) acc[mt][nt][q] = 0.f;

    // ---- GEMM1 mainloop ----
    for (int c = 0; c < NC1; c++) {
        const int s = c & 1;
        const uint32_t sb = sbase + s * STAGE_B;

        char* smc = sm + s * STAGE_B;
#pragma unroll
        for (int i = 0; i < 4; i++)
            conv_store(smc + A_OFF, soff[i], pA[i]);
        CPWAIT0();
        __syncthreads();

        if (c + 1 < NC1) {
            const uint32_t nb = sbase + (s ^ 1) * STAGE_B;
            const int k0 = (c + 1) * 64;
            load_hi256(nb + BH_OFF, BrowH, tid, K1, k0);
            CPCOMMIT();
#pragma unroll
            for (int i = 0; i < 4; i++)
                pA[i] = *(const float4*)(ArowF + (size_t)lr[i] * K1 + k0 + lc[i]);
        }

#pragma unroll
        for (int k16 = 0; k16 < 4; k16++) {
            uint32_t ah[2][4], bh[4][4];
#pragma unroll
            for (int mt = 0; mt < 2; mt++) {
                const int row = wm * 32 + mt * 16 + (lane & 15);
                const int kc  = k16 * 16 + (lane >> 4) * 8;
                const uint32_t off = (uint32_t)(row * 128) +
                                     (uint32_t)((kc * 2) ^ ((row & 7) << 4));
                LDSM4(ah[mt], sb + A_OFF + off);
            }
#pragma unroll
            for (int p = 0; p < 4; p++) {
                const int g    = lane >> 3;
                const int nrow = wn * 64 + p * 16 + (g >> 1) * 8 + (lane & 7);
                const int kc   = k16 * 16 + (g & 1) * 8;
                const uint32_t off = (uint32_t)(nrow * 128) +
                                     (uint32_t)((kc * 2) ^ ((nrow & 7) << 4));
                LDSM4(bh[p], sb + BH_OFF + off);
            }
#pragma unroll
            for (int mt = 0; mt < 2; mt++)
#pragma unroll
                for (int nt = 0; nt < 8; nt++) {
                    const int p = nt >> 1;
                    const int q = (nt & 1) * 2;
                    MMA_OP(acc[mt][nt], ah[mt], bh[p][q], bh[p][q + 1]);
                }
        }
        __syncthreads();
    }

    // ---- epilogue 1: bias + GELU -> h1 tile in SMEM (fp16, chunked swizzle)
#pragma unroll
    for (int mt = 0; mt < 2; mt++)
#pragma unroll
        for (int half = 0; half < 2; half++) {
            const int rl = wm * 32 + mt * 16 + (lane >> 2) + half * 8;
#pragma unroll
            for (int nt = 0; nt < 8; nt++) {
                const int col = wn * 64 + nt * 8 + (lane & 3) * 2;
                const float2 bi = *(const float2*)(down_b + col);
                float vx = gelu_exact(acc[mt][nt][half * 2] + bi.x);
                float vy = gelu_exact(acc[mt][nt][half * 2 + 1] + bi.y);
                __half2 h = __floats2half2_rn(vx, vy);
                const uint32_t off = H1_OFF + (uint32_t)((col >> 6) * 16384) +
                                     (uint32_t)(rl * 128) +
                                     (uint32_t)((((col & 63) * 2)) ^ ((rl & 7) << 4));
                *(uint32_t*)(sm + off) = *(uint32_t*)&h;
            }
        }
    __syncthreads();

    // ---- GEMM2: K=256 over h1 SMEM; B = expert_W[e] ----
#pragma unroll
    for (int mt = 0; mt < 2; mt++)
#pragma unroll
        for (int nt = 0; nt < 8; nt++)
#pragma unroll
            for (int q = 0; q < 4; q++) acc[mt][nt][q] = 0.f;

    load_hi256(sbase + BH_OFF, Brow2, tid, Av, 0);
    CPCOMMIT();

    for (int c = 0; c < 4; c++) {
        const int s = c & 1;
        const uint32_t sb = sbase + s * STAGE_B;
        CPWAIT0();
        __syncthreads();
        if (c + 1 < 4) {
            const uint32_t nb = sbase + (s ^ 1) * STAGE_B;
            load_hi256(nb + BH_OFF, Brow2, tid, Av, (c + 1) * 64);
            CPCOMMIT();
        }
#pragma unroll
        for (int k16 = 0; k16 < 4; k16++) {
            uint32_t ah[2][4], bh[4][4];
#pragma unroll
            for (int mt = 0; mt < 2; mt++) {
                const int row = wm * 32 + mt * 16 + (lane & 15);
                const int kc  = k16 * 16 + (lane >> 4) * 8;
                const uint32_t off = H1_OFF + (uint32_t)(c * 16384) +
                                     (uint32_t)(row * 128) +
                                     (uint32_t)((kc * 2) ^ ((row & 7) << 4));
                LDSM4(ah[mt], sbase + off);
            }
#pragma unroll
            for (int p = 0; p < 4; p++) {
                const int g    = lane >> 3;
                const int nrow = wn * 64 + p * 16 + (g >> 1) * 8 + (lane & 7);
                const int kc   = k16 * 16 + (g & 1) * 8;
                const uint32_t off = (uint32_t)(nrow * 128) +
                                     (uint32_t)((kc * 2) ^ ((nrow & 7) << 4));
                LDSM4(bh[p], sb + BH_OFF + off);
            }
#pragma unroll
            for (int mt = 0; mt < 2; mt++)
#pragma unroll
                for (int nt = 0; nt < 8; nt++) {
                    const int p = nt >> 1;
                    const int q = (nt & 1) * 2;
                    MMA_OP(acc[mt][nt], ah[mt], bh[p][q], bh[p][q + 1]);
                }
        }
        __syncthreads();
    }

    // ---- epilogue 2: (+b_e or passthrough) + emb -> g_h2 fp16 ----
#pragma unroll
    for (int mt = 0; mt < 2; mt++)
#pragma unroll
        for (int half = 0; half < 2; half++) {
            const int rl = wm * 32 + mt * 16 + (lane >> 2) + half * 8;
            const int r  = m0 + rl;
#pragma unroll
            for (int nt = 0; nt < 8; nt++) {
                const int col = wn * 64 + nt * 8 + (lane & 3) * 2;
                float vx, vy;
                if (valid) {
                    const float2 bi = *(const float2*)(biasp + col);
                    vx = acc[mt][nt][half * 2] + bi.x;
                    vy = acc[mt][nt][half * 2 + 1] + bi.y;
                } else {
                    const uint32_t off = H1_OFF + (uint32_t)((col >> 6) * 16384) +
                                         (uint32_t)(rl * 128) +
                                         (uint32_t)((((col & 63) * 2)) ^ ((rl & 7) << 4));
                    uint32_t ph = *(uint32_t*)(sm + off);
                    float2 fh = __half22float2(*(__half2*)&ph);
                    vx = fh.x; vy = fh.y;
                }
                const float2 em = *(const float2*)(embp + col);
                vx += em.x; vy += em.y;
                __half2 h = __floats2half2_rn(vx, vy);
                *(uint32_t*)(g_h2 + (size_t)r * Av + col) = *(uint32_t*)&h;
            }
        }
}

// ---------------------------------------------------------------------------
// Stage 3: U = h2 * up_W^T + up_b  -> g_uo fp16 (residual added in LN)
// C[128,256] blocks, 512 threads, warp tile 32x64, K=256.
// ---------------------------------------------------------------------------
__global__ __launch_bounds__(512, 1)
void hmma_s3(const float* __restrict__ bias) {
    constexpr int K = Av;
    constexpr int NC = K / 64;

    extern __shared__ char sm[];
    const uint32_t sbase = smem_u32(sm);

    const int tid  = threadIdx.x;
    const int lane = tid & 31;
    const int wid  = tid >> 5;
    const int wm   = wid & 3;
    const int wn   = wid >> 2;

    const int m0 = blockIdx.y * 128;
    const int n0 = blockIdx.x * 256;
    const __half* ArowH = g_h2 + (size_t)m0 * K;
    const __half* BrowH = g_uwh + (size_t)n0 * K;

    load_hi128(sbase + A_OFF, ArowH, tid, K, 0);
    load_hi256(sbase + BH_OFF, BrowH, tid, K, 0);
    CPCOMMIT();

    float acc[2][8][4];
#pragma unroll
    for (int mt = 0; mt < 2; mt++)
#pragma unroll
        for (int nt = 0; nt < 8; nt++)
#pragma unroll
            for (int q = 0; q < 4; q++) acc[mt][nt][q] = 0.f;

    for (int c = 0; c < NC; c++) {
        const int s = c & 1;
        const uint32_t sb = sbase + s * STAGE_B;
        CPWAIT0();
        __syncthreads();
        if (c + 1 < NC) {
            const uint32_t nb = sbase + (s ^ 1) * STAGE_B;
            const int k0 = (c + 1) * 64;
            load_hi128(nb + A_OFF, ArowH, tid, K, k0);
            load_hi256(nb + BH_OFF, BrowH, tid, K, k0);
            CPCOMMIT();
        }
#pragma unroll
        for (int k16 = 0; k16 < 4; k16++) {
            uint32_t ah[2][4], bh[4][4];
#pragma unroll
            for (int mt = 0; mt < 2; mt++) {
                const int row = wm * 32 + mt * 16 + (lane & 15);
                const int kc  = k16 * 16 + (lane >> 4) * 8;
                const uint32_t off = (uint32_t)(row * 128) +
                                     (uint32_t)((kc * 2) ^ ((row & 7) << 4));
                LDSM4(ah[mt], sb + A_OFF + off);
            }
#pragma unroll
            for (int p = 0; p < 4; p++) {
                const int g    = lane >> 3;
                const int nrow = wn * 64 + p * 16 + (g >> 1) * 8 + (lane & 7);
                const int kc   = k16 * 16 + (g & 1) * 8;
                const uint32_t off = (uint32_t)(nrow * 128) +
                                     (uint32_t)((kc * 2) ^ ((nrow & 7) << 4));
                LDSM4(bh[p], sb + BH_OFF + off);
            }
#pragma unroll
            for (int mt = 0; mt < 2; mt++)
#pragma unroll
                for (int nt = 0; nt < 8; nt++) {
                    const int p = nt >> 1;
                    const int q = (nt & 1) * 2;
                    MMA_OP(acc[mt][nt], ah[mt], bh[p][q], bh[p][q + 1]);
                }
        }
        __syncthreads();
    }

#pragma unroll
    for (int mt = 0; mt < 2; mt++)
#pragma unroll
        for (int half = 0; half < 2; half++) {
            const int r = m0 + wm * 32 + mt * 16 + (lane >> 2) + half * 8;
#pragma unroll
            for (int nt = 0; nt < 8; nt++) {
                const int col = n0 + wn * 64 + nt * 8 + (lane & 3) * 2;
                const float2 bi = *(const float2*)(bias + col);
                float vx = acc[mt][nt][half * 2] + bi.x;
                float vy = acc[mt][nt][half * 2 + 1] + bi.y;
                __half2 h = __floats2half2_rn(vx, vy);
                *(uint32_t*)(g_uo + (size_t)r * Dv + col) = *(uint32_t*)&h;
            }
        }
}

// ---------------------------------------------------------------------------
// LayerNorm over D=1024: x = fp16(U) + residual(fp32); two-pass in registers.
// ---------------------------------------------------------------------------
__global__ __launch_bounds__(256)
void ln_kernel(const float* __restrict__ residual,
               const float* __restrict__ gamma,
               const float* __restrict__ beta,
               float* __restrict__ out) {
    const int row = blockIdx.x;
    const int t = threadIdx.x;
    const uint2 uh = *(const uint2*)(g_uo + (size_t)row * Dv + t * 4);
    const float4 rs = *(const float4*)(residual + (size_t)row * Dv + t * 4);
    const float2 u0 = __half22float2(*(const __half2*)&uh.x);
    const float2 u1 = __half22float2(*(const __half2*)&uh.y);
    float4 v;
    v.x = u0.x + rs.x;
    v.y = u0.y + rs.y;
    v.z = u1.x + rs.z;
    v.w = u1.y + rs.w;

    __shared__ float red1[8];
    __shared__ float red2[8];

    float s = v.x + v.y + v.z + v.w;
#pragma unroll
    for (int o = 16; o; o >>= 1) s += __shfl_xor_sync(0xFFFFFFFFu, s, o);
    if ((t & 31) == 0) red1[t >> 5] = s;
    __syncthreads();
    float tot = 0.f;
#pragma unroll
    for (int i = 0; i < 8; i++) tot += red1[i];
    const float mu = tot * (1.0f / Dv);

    const float dx = v.x - mu, dy = v.y - mu, dz = v.z - mu, dw = v.w - mu;
    float s2 = dx * dx + dy * dy + dz * dz + dw * dw;
#pragma unroll
    for (int o = 16; o; o >>= 1) s2 += __shfl_xor_sync(0xFFFFFFFFu, s2, o);
    if ((t & 31) == 0) red2[t >> 5] = s2;
    __syncthreads();
    float tot2 = 0.f;
#pragma unroll
    for (int i = 0; i < 8; i++) tot2 += red2[i];
    const float inv = rsqrtf(tot2 * (1.0f / Dv) + 1e-5f);

    const int c = t * 4;
    const float4 gm = *(const float4*)(gamma + c);
    const float4 bt = *(const float4*)(beta + c);
    float4 o;
    o.x = dx * inv * gm.x + bt.x;
    o.y = dy * inv * gm.y + bt.y;
    o.z = dz * inv * gm.z + bt.z;
    o.w = dw * inv * gm.w + bt.w;
    *(float4*)(out + (size_t)row * Dv + c) = o;
}

// ---------------------------------------------------------------------------
extern "C" void kernel_launch(void* const* d_in, const int* in_sizes, int n_in,
                              void* d_out, int out_size) {
    const float* hidden     = (const float*)d_in[0];
    const int*   dom        = (const int*)d_in[1];
    const float* down_W     = (const float*)d_in[2];
    const float* down_b     = (const float*)d_in[3];
    const float* up_W       = (const float*)d_in[4];
    const float* up_b       = (const float*)d_in[5];
    const float* expert_W   = (const float*)d_in[6];
    const float* expert_b   = (const float*)d_in[7];
    const float* domain_emb = (const float*)d_in[8];
    const float* gamma      = (const float*)d_in[9];
    const float* beta       = (const float*)d_in[10];
    float* out = (float*)d_out;

    cudaFuncSetAttribute(fused_s12, cudaFuncAttributeMaxDynamicSharedMemorySize, SMEM_FUSED);
    cudaFuncSetAttribute(hmma_s3, cudaFuncAttributeMaxDynamicSharedMemorySize, SMEM_S3);

    prep_ids<<<1, 1>>>(dom);

    // one-time weight conversions (fp16)
    __half *dwh, *uwh, *ewh;
    cudaGetSymbolAddress((void**)&dwh, g_dwh);
    cudaGetSymbolAddress((void**)&uwh, g_uwh);
    cudaGetSymbolAddress((void**)&ewh, g_ewh);
    conv_w<<<128, 512>>>(down_W, dwh, Av * Dv / 4);
    conv_w<<<128, 512>>>(up_W, uwh, Dv * Av / 4);
    conv_w<<<256, 512>>>(expert_W, ewh, Ev * Av * Av / 4);

    // Stages 1+2 fused: down-proj + GELU + expert + emb
    fused_s12<<<dim3(1, Mrows / 128), 512, SMEM_FUSED>>>(hidden, down_b, expert_b, domain_emb);
    // Stage 3: up-proj + bias -> fp16 U
    hmma_s3<<<dim3(Dv / 256, Mrows / 128), 512, SMEM_S3>>>(up_b);
    // Stage 4: residual + LayerNorm
    ln_kernel<<<Mrows, 256>>>(hidden, gamma, beta, out);
}